// round 3
// baseline (speedup 1.0000x reference)
#include <cuda_runtime.h>
#include <cstdint>
#include <cstddef>

// ---------------- problem constants ----------------
#define T_LEN   16384
#define NTOT    131072        // 8 * 16384
#define RESC    120
#define SKIPC   240
#define NQ      256
#define NBLK    16

// ---------------- device scratch ----------------
__device__ __align__(16) float g_X   [RESC * NTOT];          // residual
__device__ __align__(16) float g_Zall[(size_t)NBLK * 128 * NTOT]; // all gated acts (pad 128 rows/layer)
__device__ __align__(16) float g_SK  [256 * NTOT];           // relu(skip_sum), padded to 256 rows
__device__ __align__(16) float g_H   [256 * NTOT];           // hidden after head1

// packed weights [K][Mpad], zero-padded
__device__ __align__(16) float g_Wfg[NBLK * 240 * 256];
__device__ __align__(16) float g_Bfg[NBLK * 256];
__device__ __align__(16) float g_Wrs[NBLK * 128 * 128];
__device__ __align__(16) float g_Brs[NBLK * 128];
__device__ __align__(16) float g_Wsk[2048 * 256];            // K = 16 layers x 128 (pad), M = 256
__device__ __align__(16) float g_Bsk[256];
__device__ __align__(16) float g_W1p[256 * 256];             // K padded 240->256
__device__ __align__(16) float g_W2p[256 * 256];

// ---------------- f32x2 helpers ----------------
#define FMA2(acc, a, b) asm("fma.rn.f32x2 %0, %1, %2, %0;" : "+l"(acc) : "l"(a), "l"(b))
#define UNPACK2(lo, hi, v) do { unsigned int _u0, _u1; \
    asm("mov.b64 {%0, %1}, %2;" : "=r"(_u0), "=r"(_u1) : "l"(v)); \
    lo = __uint_as_float(_u0); hi = __uint_as_float(_u1); } while (0)

__device__ __forceinline__ float safe_tanh(float x) {
    float ax = fabsf(x);
    float e  = __expf(-2.0f * ax);
    float t  = (1.0f - e) / (1.0f + e);
    return copysignf(t, x);
}
__device__ __forceinline__ float sigmoidf_(float x) {
    return 1.0f / (1.0f + __expf(-x));
}

// ---------------- packing kernels ----------------
__global__ void pack_fg_kernel(const float* __restrict__ Wf, const float* __restrict__ bf,
                               const float* __restrict__ Wg, const float* __restrict__ bg) {
    int idx = blockIdx.x * blockDim.x + threadIdx.x;
    const int total = NBLK * 240 * 256;
    if (idx < total) {
        int m = idx & 255;
        int k = (idx >> 8) % 240;
        int i = idx / (240 * 256);
        int c = m >> 1, isg = m & 1;
        float v = 0.0f;
        if (c < RESC) {
            int kc = k % RESC, tap = k / RESC;   // tap0 -> x[t-d], tap1 -> x[t]
            const float* src = isg ? Wg : Wf;
            v = src[(((size_t)i * RESC + c) * RESC + kc) * 2 + tap];
        }
        g_Wfg[idx] = v;
    }
    if (idx < NBLK * 256) {
        int m = idx & 255; int i = idx >> 8;
        int c = m >> 1, isg = m & 1;
        g_Bfg[idx] = (c < RESC) ? (isg ? bg[i * RESC + c] : bf[i * RESC + c]) : 0.0f;
    }
}

__global__ void pack_rs_kernel(const float* __restrict__ Wres, const float* __restrict__ bres) {
    int idx = blockIdx.x * blockDim.x + threadIdx.x;
    const int total = NBLK * 128 * 128;
    if (idx < total) {
        int m = idx & 127;
        int k = (idx >> 7) & 127;
        int i = idx >> 14;
        float v = 0.0f;
        if (k < RESC && m < RESC) v = Wres[((size_t)i * RESC + m) * RESC + k];
        g_Wrs[idx] = v;
    }
    if (idx < NBLK * 128) {
        int m = idx & 127; int i = idx >> 7;
        g_Brs[idx] = (m < RESC) ? bres[i * RESC + m] : 0.0f;
    }
}

__global__ void pack_sk_kernel(const float* __restrict__ Wskip, const float* __restrict__ bskip) {
    int idx = blockIdx.x * blockDim.x + threadIdx.x;
    const int total = 2048 * 256;
    if (idx < total) {
        int m = idx & 255;
        int k = idx >> 8;
        int layer = k >> 7, c = k & 127;
        float v = 0.0f;
        if (c < RESC && m < SKIPC)
            v = Wskip[((size_t)layer * SKIPC + m) * RESC + c];
        g_Wsk[idx] = v;
    }
    if (idx < 256) {
        float s = 0.0f;
        if (idx < SKIPC)
            for (int l = 0; l < NBLK; l++) s += bskip[l * SKIPC + idx];
        g_Bsk[idx] = s;
    }
}

__global__ void pack_heads_kernel(const float* __restrict__ W1, const float* __restrict__ W2) {
    int idx = blockIdx.x * blockDim.x + threadIdx.x;
    if (idx < 256 * 256) {
        int m = idx & 255; int k = idx >> 8;
        g_W1p[idx] = (k < 240) ? W1[(size_t)m * 240 + k] : 0.0f;
        g_W2p[idx] = W2[(size_t)m * 256 + k];
    }
}

__global__ void init_kernel(const float* __restrict__ wave,
                            const float* __restrict__ W_in,
                            const float* __restrict__ b_in) {
    int idx = blockIdx.x * blockDim.x + threadIdx.x;
    int r = idx >> 17;
    int n = idx & (NTOT - 1);
    g_X[(size_t)r * NTOT + n] = W_in[r] * wave[n] + b_in[r];
}

// ---------------- pipelined fused GEMM: CTA 128x128, thread 8x8 ----------------
// IN_MODE : 0 = dilated concat from g_X, 1 = plain
// OUT_MODE: 0 = FG (tanh*sig -> z layer), 1 = res (+= g_X), 2 = skip relu -> g_SK,
//           3 = head1 relu -> g_H, 4 = logits -> dout
template<int K, int IN_MODE, int OUT_MODE, int MP, int DALIGN>
__global__ void __launch_bounds__(256, 2) gemm_kernel(int blk, int d,
                                                      const float* __restrict__ bias_ext,
                                                      float* __restrict__ dout) {
    __shared__ float Ws[16][256];   // duplicated: Ws[k][2m] = Ws[k][2m+1] = W[k][m]
    __shared__ float Xs[16][128];

    const int tid = threadIdx.x;
    const int w = tid >> 5, l = tid & 31;
    const int my = (w >> 1) * 4 + (l >> 3);   // 0..15, row group (8 rows)
    const int nx = (w & 1) * 8 + (l & 7);     // 0..15, col group (8 cols)
    const int n0 = blockIdx.x * 128;
    const int mbase = blockIdx.y * 128;
    const bool first_tile = ((n0 & (T_LEN - 1)) == 0);

    const float* W; const float* bias; const float* Xin; float* Out;
    if (OUT_MODE == 0)      { W = g_Wfg + (size_t)blk * 240 * 256; bias = g_Bfg + blk * 256;
                              Xin = g_X; Out = g_Zall + (size_t)blk * 128 * NTOT; }
    else if (OUT_MODE == 1) { W = g_Wrs + (size_t)blk * 128 * 128; bias = g_Brs + blk * 128;
                              Xin = g_Zall + (size_t)blk * 128 * NTOT; Out = g_X; }
    else if (OUT_MODE == 2) { W = g_Wsk; bias = g_Bsk; Xin = g_Zall; Out = g_SK; }
    else if (OUT_MODE == 3) { W = g_W1p; bias = bias_ext; Xin = g_SK; Out = g_H; }
    else                    { W = g_W2p; bias = bias_ext; Xin = g_H; Out = dout; }

    unsigned long long acc[8][4];
#pragma unroll
    for (int r = 0; r < 8; r++)
#pragma unroll
        for (int c = 0; c < 4; c++) acc[r][c] = 0ull;

    float4 wst[2], xst[2];

    // ---- register-stage loader for chunk starting at kc ----
#define LOAD_CHUNK(kc) do {                                                     \
        _Pragma("unroll")                                                       \
        for (int i = 0; i < 2; i++) {                                           \
            int e4 = tid + i * 256;                                             \
            int kr = e4 >> 5, m4 = e4 & 31;                                     \
            wst[i] = *(const float4*)(W + (size_t)((kc) + kr) * MP + mbase + m4 * 4); \
        }                                                                       \
        _Pragma("unroll")                                                       \
        for (int i = 0; i < 2; i++) {                                           \
            int e4 = tid + i * 256;                                             \
            int kr = e4 >> 5, nl4 = e4 & 31;                                    \
            int kk = (kc) + kr;                                                 \
            int n = n0 + nl4 * 4;                                               \
            float4 v;                                                           \
            if (IN_MODE == 0) {                                                 \
                if (kk < RESC) {                                                \
                    const float* src = Xin + (size_t)kk * NTOT + n - d;         \
                    if (first_tile) {                                           \
                        int t = nl4 * 4;                                        \
                        v.x = (t + 0 >= d) ? src[0] : 0.0f;                     \
                        v.y = (t + 1 >= d) ? src[1] : 0.0f;                     \
                        v.z = (t + 2 >= d) ? src[2] : 0.0f;                     \
                        v.w = (t + 3 >= d) ? src[3] : 0.0f;                     \
                    } else if (DALIGN == 4) {                                   \
                        v = *(const float4*)src;                                \
                    } else if (DALIGN == 2) {                                   \
                        float2 a = *(const float2*)src;                         \
                        float2 b = *(const float2*)(src + 2);                   \
                        v.x = a.x; v.y = a.y; v.z = b.x; v.w = b.y;             \
                    } else {                                                    \
                        v.x = src[0]; v.y = src[1]; v.z = src[2]; v.w = src[3]; \
                    }                                                           \
                } else {                                                        \
                    v = *(const float4*)(Xin + (size_t)(kk - RESC) * NTOT + n); \
                }                                                               \
            } else {                                                            \
                v = *(const float4*)(Xin + (size_t)kk * NTOT + n);              \
            }                                                                   \
            xst[i] = v;                                                         \
        }                                                                       \
    } while (0)

    LOAD_CHUNK(0);

    const int NC = K / 16;
#pragma unroll 1
    for (int c = 0; c < NC; c++) {
        __syncthreads();   // previous compute done reading SMEM
        // ---- STS staged regs (W duplicated) ----
#pragma unroll
        for (int i = 0; i < 2; i++) {
            int e4 = tid + i * 256;
            int kr = e4 >> 5, m4 = e4 & 31;
            float4 v = wst[i];
            float4 a = make_float4(v.x, v.x, v.y, v.y);
            float4 b = make_float4(v.z, v.z, v.w, v.w);
            *(float4*)&Ws[kr][m4 * 8] = a;
            *(float4*)&Ws[kr][m4 * 8 + 4] = b;
        }
#pragma unroll
        for (int i = 0; i < 2; i++) {
            int e4 = tid + i * 256;
            int kr = e4 >> 5, nl4 = e4 & 31;
            *(float4*)&Xs[kr][nl4 * 4] = xst[i];
        }
        __syncthreads();
        if (c + 1 < NC) LOAD_CHUNK((c + 1) * 16);

        // ---- compute 16 k-steps ----
#pragma unroll
        for (int k = 0; k < 16; k++) {
            ulonglong2 w0 = *(const ulonglong2*)&Ws[k][my * 16];
            ulonglong2 w1 = *(const ulonglong2*)&Ws[k][my * 16 + 4];
            ulonglong2 w2 = *(const ulonglong2*)&Ws[k][my * 16 + 8];
            ulonglong2 w3 = *(const ulonglong2*)&Ws[k][my * 16 + 12];
            ulonglong2 xa = *(const ulonglong2*)&Xs[k][nx * 8];
            ulonglong2 xb = *(const ulonglong2*)&Xs[k][nx * 8 + 4];
            FMA2(acc[0][0], w0.x, xa.x); FMA2(acc[0][1], w0.x, xa.y);
            FMA2(acc[0][2], w0.x, xb.x); FMA2(acc[0][3], w0.x, xb.y);
            FMA2(acc[1][0], w0.y, xa.x); FMA2(acc[1][1], w0.y, xa.y);
            FMA2(acc[1][2], w0.y, xb.x); FMA2(acc[1][3], w0.y, xb.y);
            FMA2(acc[2][0], w1.x, xa.x); FMA2(acc[2][1], w1.x, xa.y);
            FMA2(acc[2][2], w1.x, xb.x); FMA2(acc[2][3], w1.x, xb.y);
            FMA2(acc[3][0], w1.y, xa.x); FMA2(acc[3][1], w1.y, xa.y);
            FMA2(acc[3][2], w1.y, xb.x); FMA2(acc[3][3], w1.y, xb.y);
            FMA2(acc[4][0], w2.x, xa.x); FMA2(acc[4][1], w2.x, xa.y);
            FMA2(acc[4][2], w2.x, xb.x); FMA2(acc[4][3], w2.x, xb.y);
            FMA2(acc[5][0], w2.y, xa.x); FMA2(acc[5][1], w2.y, xa.y);
            FMA2(acc[5][2], w2.y, xb.x); FMA2(acc[5][3], w2.y, xb.y);
            FMA2(acc[6][0], w3.x, xa.x); FMA2(acc[6][1], w3.x, xa.y);
            FMA2(acc[6][2], w3.x, xb.x); FMA2(acc[6][3], w3.x, xb.y);
            FMA2(acc[7][0], w3.y, xa.x); FMA2(acc[7][1], w3.y, xa.y);
            FMA2(acc[7][2], w3.y, xb.x); FMA2(acc[7][3], w3.y, xb.y);
        }
    }
#undef LOAD_CHUNK

    const int ncolb = n0 + nx * 8;

    if (OUT_MODE == 0) {
        // rows are (f,g) interleaved pairs -> z = tanh(f)*sigmoid(g)
#pragma unroll
        for (int p = 0; p < 4; p++) {
            int m = mbase + my * 8 + 2 * p;
            int c = m >> 1;
            if (c < RESC) {
                float bfv = bias[m], bgv = bias[m + 1];
#pragma unroll
                for (int cp = 0; cp < 4; cp++) {
                    float flo, fhi, glo, ghi;
                    UNPACK2(flo, fhi, acc[2 * p][cp]);
                    UNPACK2(glo, ghi, acc[2 * p + 1][cp]);
                    float2 z;
                    z.x = safe_tanh(flo + bfv) * sigmoidf_(glo + bgv);
                    z.y = safe_tanh(fhi + bfv) * sigmoidf_(ghi + bgv);
                    *(float2*)&Out[(size_t)c * NTOT + ncolb + cp * 2] = z;
                }
            }
        }
    } else if (OUT_MODE == 1) {
#pragma unroll
        for (int r = 0; r < 8; r++) {
            int m = my * 8 + r;
            if (m < RESC) {
                float bv = bias[m];
                float* tgt = &Out[(size_t)m * NTOT + ncolb];
#pragma unroll
                for (int cp = 0; cp < 4; cp++) {
                    float lo, hi;
                    UNPACK2(lo, hi, acc[r][cp]);
                    float2 cur = *(float2*)(tgt + cp * 2);
                    cur.x += lo + bv; cur.y += hi + bv;
                    *(float2*)(tgt + cp * 2) = cur;
                }
            }
        }
    } else if (OUT_MODE == 2 || OUT_MODE == 3) {
#pragma unroll
        for (int r = 0; r < 8; r++) {
            int m = mbase + my * 8 + r;
            float bv = bias[m];
#pragma unroll
            for (int cp = 0; cp < 4; cp++) {
                float lo, hi;
                UNPACK2(lo, hi, acc[r][cp]);
                float2 o;
                o.x = fmaxf(lo + bv, 0.0f);
                o.y = fmaxf(hi + bv, 0.0f);
                *(float2*)&Out[(size_t)m * NTOT + ncolb + cp * 2] = o;
            }
        }
    } else {
        int b = n0 >> 14;
        int t0 = ncolb & (T_LEN - 1);
#pragma unroll
        for (int r = 0; r < 8; r++) {
            int m = mbase + my * 8 + r;
            float bv = bias[m];
#pragma unroll
            for (int cp = 0; cp < 4; cp++) {
                float lo, hi;
                UNPACK2(lo, hi, acc[r][cp]);
                float2 o; o.x = lo + bv; o.y = hi + bv;
                *(float2*)&Out[((size_t)b * NQ + m) * T_LEN + t0 + cp * 2] = o;
            }
        }
    }
}

// ---------------- launch ----------------
extern "C" void kernel_launch(void* const* d_in, const int* in_sizes, int n_in,
                              void* d_out, int out_size) {
    const float* wave  = (const float*)d_in[0];
    const float* W_in  = (const float*)d_in[1];
    const float* b_in  = (const float*)d_in[2];
    const float* Wf    = (const float*)d_in[3];
    const float* bf    = (const float*)d_in[4];
    const float* Wg    = (const float*)d_in[5];
    const float* bg    = (const float*)d_in[6];
    const float* Wres  = (const float*)d_in[7];
    const float* bres  = (const float*)d_in[8];
    const float* Wskip = (const float*)d_in[9];
    const float* bskip = (const float*)d_in[10];
    const float* W1    = (const float*)d_in[11];
    const float* b1    = (const float*)d_in[12];
    const float* W2    = (const float*)d_in[13];
    const float* b2    = (const float*)d_in[14];
    float* out = (float*)d_out;

    pack_fg_kernel<<<(NBLK * 240 * 256 + 255) / 256, 256>>>(Wf, bf, Wg, bg);
    pack_rs_kernel<<<(NBLK * 128 * 128 + 255) / 256, 256>>>(Wres, bres);
    pack_sk_kernel<<<(2048 * 256 + 255) / 256, 256>>>(Wskip, bskip);
    pack_heads_kernel<<<(256 * 256 + 255) / 256, 256>>>(W1, W2);
    init_kernel<<<(RESC * NTOT) / 256, 256>>>(wave, W_in, b_in);

    static const int dil[NBLK] = {1, 2, 4, 8, 16, 32, 64, 128,
                                  1, 2, 4, 8, 16, 32, 64, 128};

    dim3 gFG(NTOT / 128, 2);
    dim3 gRS(NTOT / 128, 1);
    dim3 gH (NTOT / 128, 2);

    for (int i = 0; i < NBLK; i++) {
        int d = dil[i];
        if (d == 1)
            gemm_kernel<240, 0, 0, 256, 1><<<gFG, 256>>>(i, d, nullptr, nullptr);
        else if (d == 2)
            gemm_kernel<240, 0, 0, 256, 2><<<gFG, 256>>>(i, d, nullptr, nullptr);
        else
            gemm_kernel<240, 0, 0, 256, 4><<<gFG, 256>>>(i, d, nullptr, nullptr);
        gemm_kernel<128, 1, 1, 128, 4><<<gRS, 256>>>(i, 0, nullptr, nullptr);
    }
    gemm_kernel<2048, 1, 2, 256, 4><<<gH, 256>>>(0, 0, nullptr, nullptr);  // big skip GEMM
    gemm_kernel<256, 1, 3, 256, 4><<<gH, 256>>>(0, 0, b1, nullptr);        // head1
    gemm_kernel<256, 1, 4, 256, 4><<<gH, 256>>>(0, 0, b2, out);            // head2 -> logits
}